// round 6
// baseline (speedup 1.0000x reference)
#include <cuda_runtime.h>

// ContourChamferLoss on GB300 (sm_103a) — round 6
// Round-3 pass structure (compile-time CHUNK=500, 640 blocks, OWN_T=2)
// + fused last-block reduce with acq_rel fences.
// d^2 = pn - 2 * max_j (dot - rn/2)

#define NP_TOT 64000
#define NR_TOT 80000
#define NP     8000
#define NR     10000
#define NTOT   (NP + NR)

#define TPB   256
#define OWN_T 2
#define OTILE (TPB * OWN_T)            // 512 owners per block
#define CHUNK 500                      // compile-time; 10000/500=20, 8000/500=16 exact

#define P1_OT 16                       // ceil(8000/512)
#define P1_CH 20                       // 10000/500
#define P2_OT 20                       // ceil(10000/512)
#define P2_CH 16                       // 8000/500
#define P1_BLOCKS (P1_OT * P1_CH)      // 320
#define P2_BLOCKS (P2_OT * P2_CH)      // 320
#define GRID  (P1_BLOCKS + P2_BLOCKS)  // 640

// exact f32 replication of jnp.linspace(0, n-1, n//8) index math
#define DELTA_P ((float)(NP_TOT - 1) / (float)(NP - 1))
#define DELTA_R ((float)(NR_TOT - 1) / (float)(NR - 1))

#define NEG_BIG (-3.0e38f)

// ---- device scratch (static zero-init; no allocation) ----
// g_max zero-init: order-encoded 0 is below the encoding of any finite float,
// so 0 acts as -inf for atomicMax. Deterministic inputs -> replay-stable.
__device__ unsigned int g_max[NTOT];   // [0,NP): render-side, [NP,NTOT): ref-side
__device__ float        g_pn[NTOT];    // centered squared norms of owner points
__device__ unsigned int g_ctr;         // completion ticket (reset by last block)

typedef unsigned long long u64;

__device__ __forceinline__ u64 pk2(float a, float b) {
    u64 r; asm("mov.b64 %0, {%1, %2};" : "=l"(r) : "f"(a), "f"(b)); return r;
}
__device__ __forceinline__ void upk2(float& a, float& b, u64 v) {
    asm("mov.b64 {%0, %1}, %2;" : "=f"(a), "=f"(b) : "l"(v));
}
__device__ __forceinline__ u64 fma2(u64 a, u64 b, u64 c) {
    u64 r; asm("fma.rn.f32x2 %0, %1, %2, %3;" : "=l"(r) : "l"(a), "l"(b), "l"(c)); return r;
}

// order-preserving float<->uint map (handles negatives)
__device__ __forceinline__ unsigned int enc_f(float f) {
    unsigned int b = __float_as_uint(f);
    return (b & 0x80000000u) ? ~b : (b | 0x80000000u);
}
__device__ __forceinline__ float dec_f(unsigned int e) {
    unsigned int b = (e & 0x80000000u) ? (e & 0x7FFFFFFFu) : ~e;
    return __uint_as_float(b);
}

__global__ __launch_bounds__(TPB) void chamfer_kernel(const float* __restrict__ pc,
                                                      const float* __restrict__ ref,
                                                      float* __restrict__ out) {
    __shared__ __align__(16) float sx[CHUNK];
    __shared__ __align__(16) float sy[CHUNK];
    __shared__ __align__(16) float sc[CHUNK];

    int b = blockIdx.x;
    const float *own, *lp;
    float dOwn, dLoop;
    int nOwn, otile, cidx, goff;

    if (b < P1_BLOCKS) {
        otile = b % P1_OT; cidx = b / P1_OT;
        own = pc;  lp = ref;  dOwn = DELTA_P; dLoop = DELTA_R;
        nOwn = NP; goff = 0;
    } else {
        int bb = b - P1_BLOCKS;
        otile = bb % P2_OT; cidx = bb / P2_OT;
        own = ref; lp = pc;  dOwn = DELTA_R; dLoop = DELTA_P;
        nOwn = NR; goff = NP;
    }

    // ---- gather loop-side chunk (exact tiling, no padding branch) ----
    int base = cidx * CHUNK;
    for (int t = threadIdx.x; t < CHUNK; t += TPB) {
        int j = (int)((float)(base + t) * dLoop);
        float2 p = *reinterpret_cast<const float2*>(lp + 2 * j);
        float x = p.x - 0.5f, y = p.y - 0.5f;
        sx[t] = x; sy[t] = y;
        sc[t] = -0.5f * (x * x + y * y);
    }
    __syncthreads();

    // ---- two owner points per thread (clamped gather; invalid never written) ----
    int i0 = otile * OTILE + threadIdx.x;
    int i1 = i0 + TPB;
    int ic0 = i0 < nOwn ? i0 : 0;
    int ic1 = i1 < nOwn ? i1 : 0;
    int ig0 = (int)((float)ic0 * dOwn);
    int ig1 = (int)((float)ic1 * dOwn);
    float2 p0 = *reinterpret_cast<const float2*>(own + 2 * ig0);
    float2 p1 = *reinterpret_cast<const float2*>(own + 2 * ig1);
    float px0 = p0.x - 0.5f, py0 = p0.y - 0.5f;
    float px1 = p1.x - 0.5f, py1 = p1.y - 0.5f;

    u64 pxx0 = pk2(px0, px0), pyy0 = pk2(py0, py0);
    u64 pxx1 = pk2(px1, px1), pyy1 = pk2(py1, py1);

    // chunk-0 blocks publish owner squared norms (single writer per slot)
    if (cidx == 0) {
        if (i0 < nOwn) g_pn[goff + i0] = px0 * px0 + py0 * py0;
        if (i1 < nOwn) g_pn[goff + i1] = px1 * px1 + py1 * py1;
    }

    float m00 = NEG_BIG, m01 = NEG_BIG, m02 = NEG_BIG, m03 = NEG_BIG;
    float m10 = NEG_BIG, m11 = NEG_BIG, m12 = NEG_BIG, m13 = NEG_BIG;

    // ---- main loop: constant trip count (125 iters), round-3 proven codegen ----
    #pragma unroll 4
    for (int jj = 0; jj < CHUNK; jj += 4) {
        ulonglong2 X = *reinterpret_cast<const ulonglong2*>(&sx[jj]);
        ulonglong2 Y = *reinterpret_cast<const ulonglong2*>(&sy[jj]);
        ulonglong2 C = *reinterpret_cast<const ulonglong2*>(&sc[jj]);
        float a, c;

        upk2(a, c, fma2(pxx0, X.x, fma2(pyy0, Y.x, C.x)));
        m00 = fmaxf(m00, a);  m01 = fmaxf(m01, c);
        upk2(a, c, fma2(pxx0, X.y, fma2(pyy0, Y.y, C.y)));
        m02 = fmaxf(m02, a);  m03 = fmaxf(m03, c);

        upk2(a, c, fma2(pxx1, X.x, fma2(pyy1, Y.x, C.x)));
        m10 = fmaxf(m10, a);  m11 = fmaxf(m11, c);
        upk2(a, c, fma2(pxx1, X.y, fma2(pyy1, Y.y, C.y)));
        m12 = fmaxf(m12, a);  m13 = fmaxf(m13, c);
    }

    float m0 = fmaxf(fmaxf(m00, m01), fmaxf(m02, m03));
    float m1 = fmaxf(fmaxf(m10, m11), fmaxf(m12, m13));
    if (i0 < nOwn) atomicMax(&g_max[goff + i0], enc_f(m0));
    if (i1 < nOwn) atomicMax(&g_max[goff + i1], enc_f(m1));

    // ---- completion ticket (acq_rel, no sc fence); last block reduces ----
    __syncthreads();
    __shared__ int last;
    if (threadIdx.x == 0) {
        asm volatile("fence.acq_rel.gpu;" ::: "memory");   // release our atomics
        unsigned int done = atomicAdd(&g_ctr, 1u);
        last = (done == GRID - 1) ? 1 : 0;
    }
    __syncthreads();

    if (last) {
        if (threadIdx.x == 0)
            asm volatile("fence.acq_rel.gpu;" ::: "memory"); // acquire others' atomics
        __syncthreads();

        int tid = threadIdx.x;
        float acc = 0.f;
        #pragma unroll 4
        for (int k = tid; k < NTOT; k += TPB) {
            float s  = dec_f(__ldcg(&g_max[k]));
            float pn = __ldcg(&g_pn[k]);
            float d2 = fmaxf(fmaf(-2.f, s, pn), 0.f);
            float scale = (k < NP) ? (0.5f / (float)NP) : (0.5f / (float)NR);
            acc += sqrtf(d2) * scale;
        }

        #pragma unroll
        for (int o = 16; o > 0; o >>= 1)
            acc += __shfl_xor_sync(0xFFFFFFFFu, acc, o);

        __shared__ float sw[TPB / 32];
        if ((tid & 31) == 0) sw[tid >> 5] = acc;
        __syncthreads();

        if (tid < 32) {
            float v = (tid < TPB / 32) ? sw[tid] : 0.f;
            #pragma unroll
            for (int o = 4; o > 0; o >>= 1)
                v += __shfl_xor_sync(0xFFFFFFFFu, v, o);
            if (tid == 0) {
                out[0] = v;
                g_ctr = 0;   // reset for next graph replay
            }
        }
    }
}

extern "C" void kernel_launch(void* const* d_in, const int* in_sizes, int n_in,
                              void* d_out, int out_size) {
    const float* pc  = (const float*)d_in[0];   // img_render_points (64000 x 2)
    const float* ref = (const float*)d_in[1];   // ref point cloud   (80000 x 2)

    chamfer_kernel<<<GRID, TPB>>>(pc, ref, (float*)d_out);
}

// round 7
// speedup vs baseline: 1.0775x; 1.0775x over previous
#include <cuda_runtime.h>

// ContourChamferLoss on GB300 (sm_103a) — round 7
// Pure scalar FFMA mainloop (no inline asm in hot path).
// d^2 = pn - 2 * max_j (dot - rn/2);  s = px*x + py*y + c,  c = -0.5*(x^2+y^2)
// OWN_T=4 owners/thread, 294 blocks, fused last-block reduce.

#define NP_TOT 64000
#define NR_TOT 80000
#define NP     8000
#define NR     10000
#define NTOT   (NP + NR)

#define TPB   256
#define OWN_T 4
#define OTILE (TPB * OWN_T)            // 1024 owners per block

#define P1_OT 8                        // ceil(8000/1024)
#define P1_CH 18
#define CH1   556                      // ceil(10000/18) -> mult of 4
#define P2_OT 10                       // ceil(10000/1024)
#define P2_CH 15
#define CH2   536                      // ceil(8000/15) -> mult of 4
#define P1_BLOCKS (P1_OT * P1_CH)      // 144
#define P2_BLOCKS (P2_OT * P2_CH)      // 150
#define GRID  (P1_BLOCKS + P2_BLOCKS)  // 294
#define SCH   556

// exact f32 replication of jnp.linspace(0, n-1, n//8) index math
#define DELTA_P ((float)(NP_TOT - 1) / (float)(NP - 1))
#define DELTA_R ((float)(NR_TOT - 1) / (float)(NR - 1))

#define NEG_BIG (-3.0e38f)

// ---- device scratch (static zero-init; no allocation) ----
// g_max zero-init: order-encoded 0 is below the encoding of any finite float,
// so 0 acts as -inf for atomicMax. Deterministic inputs -> replay-stable.
__device__ unsigned int g_max[NTOT];   // [0,NP): render-side, [NP,NTOT): ref-side
__device__ float        g_pn[NTOT];    // centered squared norms of owner points
__device__ unsigned int g_ctr;         // completion ticket (reset by last block)

// order-preserving float<->uint map (handles negatives)
__device__ __forceinline__ unsigned int enc_f(float f) {
    unsigned int b = __float_as_uint(f);
    return (b & 0x80000000u) ? ~b : (b | 0x80000000u);
}
__device__ __forceinline__ float dec_f(unsigned int e) {
    unsigned int b = (e & 0x80000000u) ? (e & 0x7FFFFFFFu) : ~e;
    return __uint_as_float(b);
}

__global__ __launch_bounds__(TPB) void chamfer_kernel(const float* __restrict__ pc,
                                                      const float* __restrict__ ref,
                                                      float* __restrict__ out) {
    __shared__ __align__(16) float sx[SCH];
    __shared__ __align__(16) float sy[SCH];
    __shared__ __align__(16) float sc[SCH];

    int b = blockIdx.x;
    const float *own, *lp;
    float dOwn, dLoop;
    int nOwn, nLoop, otile, cidx, goff, chBase;

    if (b < P1_BLOCKS) {
        otile = b % P1_OT; cidx = b / P1_OT;
        own = pc;  lp = ref;  dOwn = DELTA_P; dLoop = DELTA_R;
        nOwn = NP; nLoop = NR; goff = 0; chBase = CH1;
    } else {
        int bb = b - P1_BLOCKS;
        otile = bb % P2_OT; cidx = bb / P2_OT;
        own = ref; lp = pc;  dOwn = DELTA_R; dLoop = DELTA_P;
        nOwn = NR; nLoop = NP; goff = NP; chBase = CH2;
    }

    // ---- gather loop-side chunk: center, precompute c = -0.5*(x^2+y^2) ----
    int start = cidx * chBase;
    for (int t = threadIdx.x; t < chBase; t += TPB) {
        int src = start + t;
        if (src < nLoop) {
            int j = (int)((float)src * dLoop);
            float2 p = *reinterpret_cast<const float2*>(lp + 2 * j);
            float x = p.x - 0.5f, y = p.y - 0.5f;
            sx[t] = x; sy[t] = y;
            sc[t] = -0.5f * (x * x + y * y);
        } else {
            sx[t] = 0.f; sy[t] = 0.f; sc[t] = NEG_BIG;  // sentinel: never wins max
        }
    }
    __syncthreads();

    // ---- four owner points per thread (clamped gather; invalid never written) ----
    int i0 = otile * OTILE + threadIdx.x;
    float px[OWN_T], py[OWN_T];
    #pragma unroll
    for (int o = 0; o < OWN_T; o++) {
        int i = i0 + o * TPB;
        int ic = i < nOwn ? i : 0;
        int ig = (int)((float)ic * dOwn);
        float2 p = *reinterpret_cast<const float2*>(own + 2 * ig);
        px[o] = p.x - 0.5f;
        py[o] = p.y - 0.5f;
        if (cidx == 0 && i < nOwn)        // single writer per slot
            g_pn[goff + i] = px[o] * px[o] + py[o] * py[o];
    }

    float ma[OWN_T], mb[OWN_T];
    #pragma unroll
    for (int o = 0; o < OWN_T; o++) { ma[o] = NEG_BIG; mb[o] = NEG_BIG; }

    // ---- main loop: scalar FFMA, 4 loop pts x 4 owners per iter ----
    // per iter: 3 LDS.128 + 32 FFMA + 24 FMNMX  (16 pairs)
    #pragma unroll 2
    for (int jj = 0; jj < chBase; jj += 4) {
        float4 X = *reinterpret_cast<const float4*>(&sx[jj]);
        float4 Y = *reinterpret_cast<const float4*>(&sy[jj]);
        float4 C = *reinterpret_cast<const float4*>(&sc[jj]);

        #pragma unroll
        for (int o = 0; o < OWN_T; o++) {
            float s0 = fmaf(px[o], X.x, fmaf(py[o], Y.x, C.x));
            float s1 = fmaf(px[o], X.y, fmaf(py[o], Y.y, C.y));
            float s2 = fmaf(px[o], X.z, fmaf(py[o], Y.z, C.z));
            float s3 = fmaf(px[o], X.w, fmaf(py[o], Y.w, C.w));
            ma[o] = fmaxf(ma[o], fmaxf(s0, s1));
            mb[o] = fmaxf(mb[o], fmaxf(s2, s3));
        }
    }

    #pragma unroll
    for (int o = 0; o < OWN_T; o++) {
        int i = i0 + o * TPB;
        if (i < nOwn)
            atomicMax(&g_max[goff + i], enc_f(fmaxf(ma[o], mb[o])));
    }

    // ---- completion ticket; last-arriving block reduces ----
    __syncthreads();
    __shared__ int lastf;
    if (threadIdx.x == 0) {
        __threadfence();
        unsigned int done = atomicAdd(&g_ctr, 1u);
        lastf = (done == GRID - 1) ? 1 : 0;
    }
    __syncthreads();

    if (lastf) {
        int tid = threadIdx.x;
        float acc = 0.f;
        #pragma unroll 4
        for (int k = tid; k < NTOT; k += TPB) {
            float s  = dec_f(__ldcg(&g_max[k]));
            float pn = __ldcg(&g_pn[k]);
            float d2 = fmaxf(fmaf(-2.f, s, pn), 0.f);
            float scale = (k < NP) ? (0.5f / (float)NP) : (0.5f / (float)NR);
            acc += sqrtf(d2) * scale;
        }

        #pragma unroll
        for (int o = 16; o > 0; o >>= 1)
            acc += __shfl_xor_sync(0xFFFFFFFFu, acc, o);

        __shared__ float sw[TPB / 32];
        if ((tid & 31) == 0) sw[tid >> 5] = acc;
        __syncthreads();

        if (tid < 32) {
            float v = (tid < TPB / 32) ? sw[tid] : 0.f;
            #pragma unroll
            for (int o = 4; o > 0; o >>= 1)
                v += __shfl_xor_sync(0xFFFFFFFFu, v, o);
            if (tid == 0) {
                out[0] = v;
                g_ctr = 0;   // reset for next graph replay
            }
        }
    }
}

extern "C" void kernel_launch(void* const* d_in, const int* in_sizes, int n_in,
                              void* d_out, int out_size) {
    const float* pc  = (const float*)d_in[0];   // img_render_points (64000 x 2)
    const float* ref = (const float*)d_in[1];   // ref point cloud   (80000 x 2)

    chamfer_kernel<<<GRID, TPB>>>(pc, ref, (float*)d_out);
}

// round 8
// speedup vs baseline: 1.9680x; 1.8264x over previous
#include <cuda_runtime.h>

// ContourChamferLoss on GB300 (sm_103a) — round 8
// Exact nearest-neighbor via 32x32 spatial grid + expanding-ring search.
// Brute force (160M pairs) -> ~1.4M candidate pairs.

#define NP_TOT 64000
#define NR_TOT 80000
#define NP     8000
#define NR     10000

// exact f32 replication of jnp.linspace(0, n-1, n//8) index math
#define DELTA_P ((float)(NP_TOT - 1) / (float)(NP - 1))
#define DELTA_R ((float)(NR_TOT - 1) / (float)(NR - 1))

#define GK    32                 // grid cells per dimension
#define NCELL (GK * GK)          // 1024
#define CS    (1.0f / (float)GK) // cell size
#define CAP   128                // slots per cell (mean ~10; overflow prob ~0)

#define STPB     256
#define S_BLOCKS ((NP + NR + STPB - 1) / STPB)   // 71

#define TPB       128
#define P1_BLOCKS ((NP + TPB - 1) / TPB)         // 63  (owners: render pts, search ref grid)
#define P2_BLOCKS ((NR + TPB - 1) / TPB)         // 79  (owners: ref pts, search render grid)
#define NBLK      (P1_BLOCKS + P2_BLOCKS)        // 142

// ---- device scratch (static zero-init; no allocation allowed) ----
// Counters start zero (static init) and are re-zeroed by the last search block
// each run -> graph replays always see zeroed counters. Slot order within a
// cell may vary run-to-run, but min over a set is order-independent -> output
// is deterministic.
__device__ int    g_cntP[NCELL];
__device__ int    g_cntR[NCELL];
__device__ float2 g_ptsP[NCELL * CAP];   // bucketed subsampled render points
__device__ float2 g_ptsR[NCELL * CAP];   // bucketed subsampled ref points
__device__ float  g_part[NBLK];
__device__ unsigned int g_ctr;

__device__ __forceinline__ int clamp_cell(int c) {
    return c < 0 ? 0 : (c > GK - 1 ? GK - 1 : c);
}

// ---------------- scatter: subsample gather + bucket append ----------------
__global__ __launch_bounds__(STPB) void scatter_kernel(const float* __restrict__ pc,
                                                       const float* __restrict__ ref) {
    int k = blockIdx.x * STPB + threadIdx.x;
    if (k < NP) {
        int i = (int)((float)k * DELTA_P);
        float2 p = *reinterpret_cast<const float2*>(pc + 2 * i);
        int cx = clamp_cell((int)(p.x * (float)GK));
        int cy = clamp_cell((int)(p.y * (float)GK));
        int c = cy * GK + cx;
        int s = atomicAdd(&g_cntP[c], 1);
        if (s < CAP) g_ptsP[c * CAP + s] = p;
    } else if (k < NP + NR) {
        int j = k - NP;
        int i = (int)((float)j * DELTA_R);
        float2 p = *reinterpret_cast<const float2*>(ref + 2 * i);
        int cx = clamp_cell((int)(p.x * (float)GK));
        int cy = clamp_cell((int)(p.y * (float)GK));
        int c = cy * GK + cx;
        int s = atomicAdd(&g_cntR[c], 1);
        if (s < CAP) g_ptsR[c * CAP + s] = p;
    }
}

// scan all candidates in one cell, update dmin
__device__ __forceinline__ void scan_cell(const float2* __restrict__ pts,
                                          const int* __restrict__ cnt,
                                          int c, float px, float py, float& dmin) {
    int m = cnt[c];
    m = m < CAP ? m : CAP;
    const float2* q = pts + c * CAP;
    for (int t = 0; t < m; t++) {
        float2 pp = q[t];
        float ddx = px - pp.x;
        float ddy = py - pp.y;
        float d2 = fmaf(ddx, ddx, ddy * ddy);
        dmin = fminf(dmin, d2);
    }
}

// ---------------- search: exact NN per owner + fused reduction ----------------
__global__ __launch_bounds__(TPB) void search_kernel(const float* __restrict__ pc,
                                                     const float* __restrict__ ref,
                                                     float* __restrict__ out) {
    int b = blockIdx.x;
    const float2* pts;
    const int* cnt;
    const float* own;
    float delta, scale;
    int n, base;

    if (b < P1_BLOCKS) {
        pts = g_ptsR; cnt = g_cntR; own = pc;
        delta = DELTA_P; n = NP; scale = 0.5f / (float)NP;
        base = b * TPB;
    } else {
        pts = g_ptsP; cnt = g_cntP; own = ref;
        delta = DELTA_R; n = NR; scale = 0.5f / (float)NR;
        base = (b - P1_BLOCKS) * TPB;
    }

    int k = base + threadIdx.x;
    float v = 0.f;
    if (k < n) {
        int i = (int)((float)k * delta);
        float2 p = *reinterpret_cast<const float2*>(own + 2 * i);
        float px = p.x, py = p.y;
        int cx = clamp_cell((int)(px * (float)GK));
        int cy = clamp_cell((int)(py * (float)GK));

        float dmin = 1e30f;

        // radius-1 square (3x3, clipped) — exact for dmin <= CS with prob ~1
        int x0 = clamp_cell(cx - 1), x1 = clamp_cell(cx + 1);
        int y0 = clamp_cell(cy - 1), y1 = clamp_cell(cy + 1);
        for (int yy = y0; yy <= y1; yy++)
            for (int xx = x0; xx <= x1; xx++)
                scan_cell(pts, cnt, yy * GK + xx, px, py, dmin);

        // expanding rings: after scanning Chebyshev-radius-r square, coverage
        // radius is r*CS; stop when dmin <= (r*CS)^2. r=31 covers the full grid.
        int r = 1;
        float cov = CS;
        while (dmin > cov * cov && r < GK - 1) {
            r++;
            cov = (float)r * CS;
            for (int dy = -r; dy <= r; dy++) {
                int yy = cy + dy;
                if (yy < 0 || yy >= GK) continue;
                if (dy == -r || dy == r) {
                    for (int dx = -r; dx <= r; dx++) {
                        int xx = cx + dx;
                        if (xx < 0 || xx >= GK) continue;
                        scan_cell(pts, cnt, yy * GK + xx, px, py, dmin);
                    }
                } else {
                    int xx = cx - r;
                    if (xx >= 0) scan_cell(pts, cnt, yy * GK + xx, px, py, dmin);
                    xx = cx + r;
                    if (xx < GK) scan_cell(pts, cnt, yy * GK + xx, px, py, dmin);
                }
            }
        }

        v = sqrtf(dmin) * scale;
    }

    // ---- block reduce (deterministic order) ----
    #pragma unroll
    for (int o = 16; o > 0; o >>= 1)
        v += __shfl_xor_sync(0xFFFFFFFFu, v, o);

    __shared__ float sw[TPB / 32];
    int lane = threadIdx.x & 31, wid = threadIdx.x >> 5;
    if (lane == 0) sw[wid] = v;
    __syncthreads();

    __shared__ int lastf;
    if (threadIdx.x == 0) {
        float s = sw[0] + sw[1] + sw[2] + sw[3];
        g_part[b] = s;
        __threadfence();
        unsigned int done = atomicAdd(&g_ctr, 1u);
        lastf = (done == NBLK - 1) ? 1 : 0;
    }
    __syncthreads();

    // ---- last-arriving block: final combine + reset state for next replay ----
    if (lastf) {
        if (threadIdx.x == 0) __threadfence();
        __syncthreads();

        int tid = threadIdx.x;
        float a = (tid < NBLK) ? g_part[tid] : 0.f;
        float bb2 = (tid + TPB < NBLK) ? g_part[tid + TPB] : 0.f;
        float acc = a + bb2;

        #pragma unroll
        for (int o = 16; o > 0; o >>= 1)
            acc += __shfl_xor_sync(0xFFFFFFFFu, acc, o);
        if (lane == 0) sw[wid] = acc;
        __syncthreads();

        if (tid == 0) {
            out[0] = sw[0] + sw[1] + sw[2] + sw[3];
            g_ctr = 0;
        }

        // zero bucket counters for the next graph replay (all readers finished)
        for (int c = tid; c < NCELL; c += TPB) {
            g_cntP[c] = 0;
            g_cntR[c] = 0;
        }
    }
}

extern "C" void kernel_launch(void* const* d_in, const int* in_sizes, int n_in,
                              void* d_out, int out_size) {
    const float* pc  = (const float*)d_in[0];   // img_render_points (64000 x 2)
    const float* ref = (const float*)d_in[1];   // ref point cloud   (80000 x 2)

    scatter_kernel<<<S_BLOCKS, STPB>>>(pc, ref);
    search_kernel<<<NBLK, TPB>>>(pc, ref, (float*)d_out);
}